// round 11
// baseline (speedup 1.0000x reference)
#include <cuda_runtime.h>

// CAN co-action unit: per-sample 2-layer MLP, D=16, N=50, B=16384.
// R3 champion data path with the smem/sync apparatus removed entirely:
// weights are read directly from global memory via __ldg (all 25 threads of a
// sample read identical addresses -> L1-resident broadcast; params 17.6KB/CTA
// vs 228KB L1). No staging loop, no __syncthreads, no shared memory: every
// warp is an independent straight-line stream. Otherwise identical to R3:
// 2 same-sample rows/thread in registers, scalar fmaf, strided x LDG.128,
// fire-and-forget STG.128, 224 threads / 8 samples per CTA.

#define D 16
#define N 50
#define PARAMS 544            // 2*(256+16)
#define SPC 8                 // samples per CTA
#define TPS 25                // threads per sample (2 rows each)
#define THREADS 224
#define ACTIVE (SPC * TPS)    // 200
#define CTA_ROWS (SPC * N)    // 400

__global__ __launch_bounds__(THREADS, 3) void can_kernel(
    const float* __restrict__ user_emb,
    const float* __restrict__ item_emb,
    float* __restrict__ out)
{
    const int t = threadIdx.x;
    if (t >= ACTIVE) return;                  // no barrier -> exit immediately

    const int s = t / TPS;                    // sample in CTA
    const int j = t - s * TPS;                // 0..24

    // Per-sample param block in global memory (L1-cached, broadcast reads).
    const float* p = item_emb + ((size_t)blockIdx.x * SPC + s) * PARAMS;

    // ---- This thread's two rows (same sample): rows j and j+25.
    const size_t grow = (size_t)blockIdx.x * CTA_ROWS + s * N + j;
    float x0[D], x1[D];
    {
        const float4* r0 = (const float4*)(user_emb + grow * D);
        const float4* r1 = (const float4*)(user_emb + (grow + TPS) * D);
        #pragma unroll
        for (int q = 0; q < 4; q++) {
            float4 a = __ldg(r0 + q), b = __ldg(r1 + q);
            x0[q*4+0]=a.x; x0[q*4+1]=a.y; x0[q*4+2]=a.z; x0[q*4+3]=a.w;
            x1[q*4+0]=b.x; x1[q*4+1]=b.y; x1[q*4+2]=b.z; x1[q*4+3]=b.w;
        }
    }

    float a0[D], a1[D];

    // ---- Layer 1: relu(x W0 + b0).  W0 = p[0..255], b0 = p[256..271].
    {
        const float4* bias = (const float4*)(p + 256);
        #pragma unroll
        for (int q = 0; q < 4; q++) {
            float4 v = __ldg(bias + q);
            a0[q*4+0]=v.x; a0[q*4+1]=v.y; a0[q*4+2]=v.z; a0[q*4+3]=v.w;
            a1[q*4+0]=v.x; a1[q*4+1]=v.y; a1[q*4+2]=v.z; a1[q*4+3]=v.w;
        }
        #pragma unroll
        for (int d = 0; d < D; d++) {
            const float4* wr = (const float4*)(p + d * D);
            const float u0 = x0[d], u1 = x1[d];
            #pragma unroll
            for (int q = 0; q < 4; q++) {
                float4 w = __ldg(wr + q);
                a0[q*4+0]=fmaf(u0,w.x,a0[q*4+0]); a1[q*4+0]=fmaf(u1,w.x,a1[q*4+0]);
                a0[q*4+1]=fmaf(u0,w.y,a0[q*4+1]); a1[q*4+1]=fmaf(u1,w.y,a1[q*4+1]);
                a0[q*4+2]=fmaf(u0,w.z,a0[q*4+2]); a1[q*4+2]=fmaf(u1,w.z,a1[q*4+2]);
                a0[q*4+3]=fmaf(u0,w.w,a0[q*4+3]); a1[q*4+3]=fmaf(u1,w.w,a1[q*4+3]);
            }
        }
        #pragma unroll
        for (int e = 0; e < D; e++) {
            x0[e] = fmaxf(a0[e], 0.0f);
            x1[e] = fmaxf(a1[e], 0.0f);
        }
    }

    // ---- Layer 2: x W1 + b1.  W1 = p[272..527], b1 = p[528..543].
    {
        const float4* bias = (const float4*)(p + 528);
        #pragma unroll
        for (int q = 0; q < 4; q++) {
            float4 v = __ldg(bias + q);
            a0[q*4+0]=v.x; a0[q*4+1]=v.y; a0[q*4+2]=v.z; a0[q*4+3]=v.w;
            a1[q*4+0]=v.x; a1[q*4+1]=v.y; a1[q*4+2]=v.z; a1[q*4+3]=v.w;
        }
        #pragma unroll
        for (int d = 0; d < D; d++) {
            const float4* wr = (const float4*)(p + 272 + d * D);
            const float u0 = x0[d], u1 = x1[d];
            #pragma unroll
            for (int q = 0; q < 4; q++) {
                float4 w = __ldg(wr + q);
                a0[q*4+0]=fmaf(u0,w.x,a0[q*4+0]); a1[q*4+0]=fmaf(u1,w.x,a1[q*4+0]);
                a0[q*4+1]=fmaf(u0,w.y,a0[q*4+1]); a1[q*4+1]=fmaf(u1,w.y,a1[q*4+1]);
                a0[q*4+2]=fmaf(u0,w.z,a0[q*4+2]); a1[q*4+2]=fmaf(u1,w.z,a1[q*4+2]);
                a0[q*4+3]=fmaf(u0,w.w,a0[q*4+3]); a1[q*4+3]=fmaf(u1,w.w,a1[q*4+3]);
            }
        }
    }

    // ---- Relu + store both rows (4x STG.128 each, fire-and-forget).
    {
        float4* o0 = (float4*)(out + grow * D);
        float4* o1 = (float4*)(out + (grow + TPS) * D);
        #pragma unroll
        for (int q = 0; q < 4; q++) {
            float4 v0 = { fmaxf(a0[q*4+0],0.f), fmaxf(a0[q*4+1],0.f),
                          fmaxf(a0[q*4+2],0.f), fmaxf(a0[q*4+3],0.f) };
            float4 v1 = { fmaxf(a1[q*4+0],0.f), fmaxf(a1[q*4+1],0.f),
                          fmaxf(a1[q*4+2],0.f), fmaxf(a1[q*4+3],0.f) };
            o0[q] = v0;
            o1[q] = v1;
        }
    }
}

extern "C" void kernel_launch(void* const* d_in, const int* in_sizes, int n_in,
                              void* d_out, int out_size) {
    const float* user_emb = (const float*)d_in[0];
    const float* item_emb = (const float*)d_in[1];
    float* out = (float*)d_out;
    const int B = in_sizes[1] / PARAMS;        // 16384
    can_kernel<<<B / SPC, THREADS>>>(user_emb, item_emb, out);
}

// round 12
// speedup vs baseline: 1.7246x; 1.7246x over previous
#include <cuda_runtime.h>

// CAN co-action unit: per-sample 2-layer MLP, D=16, N=50, B=16384.
// Warp-autonomous variant of the R3 champion: 1 warp = 1 sample. Each warp
// stages its own 544-word param block into a warp-private smem slab
// (coalesced LDG.128 -> STS.128), __syncwarp (no CTA barrier anywhere), then
// lanes 0..24 run R3's exact compute core (2 same-sample rows/thread in
// registers, broadcast LDS.128 weights - strictly uniform addresses within
// the warp, direct strided x LDG.128, fire-and-forget STG.128). Warps flow
// through load/compute/store phases independently, decorrelating DRAM bursts
// that the CTA-wide __syncthreads previously wave-synchronized.

#define D 16
#define N 50
#define PARAMS 544            // 2*(256+16) words; 2176B, 16B-aligned
#define WPC 8                 // warps (=samples) per CTA
#define THREADS (WPC * 32)    // 256
#define CTA_ROWS (WPC * N)    // 400

__global__ __launch_bounds__(THREADS, 3) void can_kernel(
    const float* __restrict__ user_emb,
    const float* __restrict__ item_emb,
    float* __restrict__ out)
{
    __shared__ float sp[WPC * PARAMS];   // per-warp param slab (no pad needed:
                                         // all compute LDS are warp-uniform)

    const int t = threadIdx.x;
    const int w = t >> 5;                // warp = sample within CTA
    const int l = t & 31;

    // ---- Warp stages its own sample's params: 136 float4, coalesced.
    float* slab = sp + w * PARAMS;
    {
        const float4* src = (const float4*)(item_emb
                            + ((size_t)blockIdx.x * WPC + w) * PARAMS);
        #pragma unroll
        for (int k = 0; k < 5; k++) {
            int i = l + 32 * k;
            if (i < PARAMS / 4)
                ((float4*)slab)[i] = src[i];
        }
    }

    // ---- This lane's two rows (lanes 0..24): rows l and l+25 of sample w.
    const bool active = (l < 25);
    const size_t grow = (size_t)blockIdx.x * CTA_ROWS + w * N + l;
    float x0[D], x1[D];
    if (active) {
        const float4* r0 = (const float4*)(user_emb + grow * D);
        const float4* r1 = (const float4*)(user_emb + (grow + 25) * D);
        #pragma unroll
        for (int q = 0; q < 4; q++) {
            float4 a = r0[q], b = r1[q];
            x0[q*4+0]=a.x; x0[q*4+1]=a.y; x0[q*4+2]=a.z; x0[q*4+3]=a.w;
            x1[q*4+0]=b.x; x1[q*4+1]=b.y; x1[q*4+2]=b.z; x1[q*4+3]=b.w;
        }
    }

    __syncwarp();                        // only warp-local visibility needed

    if (!active) return;

    const float* p = slab;
    float a0[D], a1[D];

    // ---- Layer 1: relu(x W0 + b0).  W0 = p[0..255], b0 = p[256..271].
    {
        const float4* bias = (const float4*)(p + 256);
        #pragma unroll
        for (int q = 0; q < 4; q++) {
            float4 v = bias[q];
            a0[q*4+0]=v.x; a0[q*4+1]=v.y; a0[q*4+2]=v.z; a0[q*4+3]=v.w;
            a1[q*4+0]=v.x; a1[q*4+1]=v.y; a1[q*4+2]=v.z; a1[q*4+3]=v.w;
        }
        #pragma unroll
        for (int d = 0; d < D; d++) {
            const float4* wr = (const float4*)(p + d * D);
            const float u0 = x0[d], u1 = x1[d];
            #pragma unroll
            for (int q = 0; q < 4; q++) {
                float4 wv = wr[q];
                a0[q*4+0]=fmaf(u0,wv.x,a0[q*4+0]); a1[q*4+0]=fmaf(u1,wv.x,a1[q*4+0]);
                a0[q*4+1]=fmaf(u0,wv.y,a0[q*4+1]); a1[q*4+1]=fmaf(u1,wv.y,a1[q*4+1]);
                a0[q*4+2]=fmaf(u0,wv.z,a0[q*4+2]); a1[q*4+2]=fmaf(u1,wv.z,a1[q*4+2]);
                a0[q*4+3]=fmaf(u0,wv.w,a0[q*4+3]); a1[q*4+3]=fmaf(u1,wv.w,a1[q*4+3]);
            }
        }
        #pragma unroll
        for (int e = 0; e < D; e++) {
            x0[e] = fmaxf(a0[e], 0.0f);
            x1[e] = fmaxf(a1[e], 0.0f);
        }
    }

    // ---- Layer 2: x W1 + b1.  W1 = p[272..527], b1 = p[528..543].
    {
        const float4* bias = (const float4*)(p + 528);
        #pragma unroll
        for (int q = 0; q < 4; q++) {
            float4 v = bias[q];
            a0[q*4+0]=v.x; a0[q*4+1]=v.y; a0[q*4+2]=v.z; a0[q*4+3]=v.w;
            a1[q*4+0]=v.x; a1[q*4+1]=v.y; a1[q*4+2]=v.z; a1[q*4+3]=v.w;
        }
        #pragma unroll
        for (int d = 0; d < D; d++) {
            const float4* wr = (const float4*)(p + 272 + d * D);
            const float u0 = x0[d], u1 = x1[d];
            #pragma unroll
            for (int q = 0; q < 4; q++) {
                float4 wv = wr[q];
                a0[q*4+0]=fmaf(u0,wv.x,a0[q*4+0]); a1[q*4+0]=fmaf(u1,wv.x,a1[q*4+0]);
                a0[q*4+1]=fmaf(u0,wv.y,a0[q*4+1]); a1[q*4+1]=fmaf(u1,wv.y,a1[q*4+1]);
                a0[q*4+2]=fmaf(u0,wv.z,a0[q*4+2]); a1[q*4+2]=fmaf(u1,wv.z,a1[q*4+2]);
                a0[q*4+3]=fmaf(u0,wv.w,a0[q*4+3]); a1[q*4+3]=fmaf(u1,wv.w,a1[q*4+3]);
            }
        }
    }

    // ---- Relu + store both rows (4x STG.128 each, fire-and-forget).
    {
        float4* o0 = (float4*)(out + grow * D);
        float4* o1 = (float4*)(out + (grow + 25) * D);
        #pragma unroll
        for (int q = 0; q < 4; q++) {
            float4 v0 = { fmaxf(a0[q*4+0],0.f), fmaxf(a0[q*4+1],0.f),
                          fmaxf(a0[q*4+2],0.f), fmaxf(a0[q*4+3],0.f) };
            float4 v1 = { fmaxf(a1[q*4+0],0.f), fmaxf(a1[q*4+1],0.f),
                          fmaxf(a1[q*4+2],0.f), fmaxf(a1[q*4+3],0.f) };
            o0[q] = v0;
            o1[q] = v1;
        }
    }
}

extern "C" void kernel_launch(void* const* d_in, const int* in_sizes, int n_in,
                              void* d_out, int out_size) {
    const float* user_emb = (const float*)d_in[0];
    const float* item_emb = (const float*)d_in[1];
    float* out = (float*)d_out;
    const int B = in_sizes[1] / PARAMS;        // 16384
    can_kernel<<<B / WPC, THREADS>>>(user_emb, item_emb, out);
}

// round 13
// speedup vs baseline: 1.7692x; 1.0258x over previous
#include <cuda_runtime.h>

// CAN co-action unit: per-sample 2-layer MLP, D=16, N=50, B=16384.
// R12 champion (warp-autonomous: 1 warp = 1 sample, warp-private param slab,
// __syncwarp only, lanes 0..24 x 2 rows in registers, broadcast LDS.128
// weights, strided x LDG.128, fire-and-forget STG.128) with ONE change:
// the compute core uses packed fma.rn.f32x2 (FFMA2), halving the FFMA
// instruction count that now saturates the issue/fma pipe.

#define D 16
#define N 50
#define PARAMS 544            // 2*(256+16) words; 2176B
#define WPC 8                 // warps (=samples) per CTA
#define THREADS (WPC * 32)    // 256
#define CTA_ROWS (WPC * N)    // 400

__device__ __forceinline__ unsigned long long splat2(float x) {
    unsigned long long r; unsigned u = __float_as_uint(x);
    asm("mov.b64 %0, {%1, %1};" : "=l"(r) : "r"(u));
    return r;
}
__device__ __forceinline__ void ffma2(unsigned long long& d,
                                      unsigned long long a, unsigned long long b) {
    asm("fma.rn.f32x2 %0, %1, %2, %0;" : "+l"(d) : "l"(a), "l"(b));
}
__device__ __forceinline__ void unpack2(unsigned long long v, float& lo, float& hi) {
    unsigned a, b;
    asm("mov.b64 {%0, %1}, %2;" : "=r"(a), "=r"(b) : "l"(v));
    lo = __uint_as_float(a); hi = __uint_as_float(b);
}

__global__ __launch_bounds__(THREADS, 3) void can_kernel(
    const float* __restrict__ user_emb,
    const float* __restrict__ item_emb,
    float* __restrict__ out)
{
    __shared__ float sp[WPC * PARAMS];   // warp-private slabs, uniform reads

    const int t = threadIdx.x;
    const int w = t >> 5;
    const int l = t & 31;

    // ---- Warp stages its own sample's params: 136 float4, coalesced.
    float* slab = sp + w * PARAMS;
    {
        const float4* src = (const float4*)(item_emb
                            + ((size_t)blockIdx.x * WPC + w) * PARAMS);
        #pragma unroll
        for (int k = 0; k < 5; k++) {
            int i = l + 32 * k;
            if (i < PARAMS / 4)
                ((float4*)slab)[i] = src[i];
        }
    }

    // ---- This lane's two rows (lanes 0..24): rows l and l+25 of sample w.
    const bool active = (l < 25);
    const size_t grow = (size_t)blockIdx.x * CTA_ROWS + w * N + l;
    float x0[D], x1[D];
    if (active) {
        const float4* r0 = (const float4*)(user_emb + grow * D);
        const float4* r1 = (const float4*)(user_emb + (grow + 25) * D);
        #pragma unroll
        for (int q = 0; q < 4; q++) {
            float4 a = r0[q], b = r1[q];
            x0[q*4+0]=a.x; x0[q*4+1]=a.y; x0[q*4+2]=a.z; x0[q*4+3]=a.w;
            x1[q*4+0]=b.x; x1[q*4+1]=b.y; x1[q*4+2]=b.z; x1[q*4+3]=b.w;
        }
    }

    __syncwarp();

    if (!active) return;

    const float* p = slab;
    unsigned long long a0[8], a1[8];

    // ---- Layer 1: relu(x W0 + b0).  W0 = p[0..255], b0 = p[256..271].
    {
        const ulonglong2* bp = (const ulonglong2*)(p + 256);
        #pragma unroll
        for (int h = 0; h < 4; h++) {
            ulonglong2 bv = bp[h];
            a0[2*h]=bv.x; a0[2*h+1]=bv.y;
            a1[2*h]=bv.x; a1[2*h+1]=bv.y;
        }
        #pragma unroll
        for (int d = 0; d < D; d++) {
            const ulonglong2* wr = (const ulonglong2*)(p + d * D);
            ulonglong2 wA = wr[0], wB = wr[1], wC = wr[2], wE = wr[3];
            unsigned long long u0 = splat2(x0[d]), u1 = splat2(x1[d]);
            ffma2(a0[0],u0,wA.x); ffma2(a1[0],u1,wA.x);
            ffma2(a0[1],u0,wA.y); ffma2(a1[1],u1,wA.y);
            ffma2(a0[2],u0,wB.x); ffma2(a1[2],u1,wB.x);
            ffma2(a0[3],u0,wB.y); ffma2(a1[3],u1,wB.y);
            ffma2(a0[4],u0,wC.x); ffma2(a1[4],u1,wC.x);
            ffma2(a0[5],u0,wC.y); ffma2(a1[5],u1,wC.y);
            ffma2(a0[6],u0,wE.x); ffma2(a1[6],u1,wE.x);
            ffma2(a0[7],u0,wE.y); ffma2(a1[7],u1,wE.y);
        }
        #pragma unroll
        for (int h = 0; h < 8; h++) {
            float lo, hi;
            unpack2(a0[h], lo, hi);
            x0[2*h] = fmaxf(lo, 0.0f); x0[2*h+1] = fmaxf(hi, 0.0f);
            unpack2(a1[h], lo, hi);
            x1[2*h] = fmaxf(lo, 0.0f); x1[2*h+1] = fmaxf(hi, 0.0f);
        }
    }

    // ---- Layer 2: x W1 + b1.  W1 = p[272..527], b1 = p[528..543].
    {
        const ulonglong2* bp = (const ulonglong2*)(p + 528);
        #pragma unroll
        for (int h = 0; h < 4; h++) {
            ulonglong2 bv = bp[h];
            a0[2*h]=bv.x; a0[2*h+1]=bv.y;
            a1[2*h]=bv.x; a1[2*h+1]=bv.y;
        }
        #pragma unroll
        for (int d = 0; d < D; d++) {
            const ulonglong2* wr = (const ulonglong2*)(p + 272 + d * D);
            ulonglong2 wA = wr[0], wB = wr[1], wC = wr[2], wE = wr[3];
            unsigned long long u0 = splat2(x0[d]), u1 = splat2(x1[d]);
            ffma2(a0[0],u0,wA.x); ffma2(a1[0],u1,wA.x);
            ffma2(a0[1],u0,wA.y); ffma2(a1[1],u1,wA.y);
            ffma2(a0[2],u0,wB.x); ffma2(a1[2],u1,wB.x);
            ffma2(a0[3],u0,wB.y); ffma2(a1[3],u1,wB.y);
            ffma2(a0[4],u0,wC.x); ffma2(a1[4],u1,wC.x);
            ffma2(a0[5],u0,wC.y); ffma2(a1[5],u1,wC.y);
            ffma2(a0[6],u0,wE.x); ffma2(a1[6],u1,wE.x);
            ffma2(a0[7],u0,wE.y); ffma2(a1[7],u1,wE.y);
        }
    }

    // ---- Relu + store both rows (4x STG.128 each, fire-and-forget).
    {
        float4* o0 = (float4*)(out + grow * D);
        float4* o1 = (float4*)(out + (grow + 25) * D);
        #pragma unroll
        for (int q = 0; q < 4; q++) {
            float l0,h0,l1,h1, l2,h2,l3,h3;
            unpack2(a0[2*q],   l0, h0); unpack2(a0[2*q+1], l1, h1);
            unpack2(a1[2*q],   l2, h2); unpack2(a1[2*q+1], l3, h3);
            float4 v0 = { fmaxf(l0,0.f), fmaxf(h0,0.f), fmaxf(l1,0.f), fmaxf(h1,0.f) };
            float4 v1 = { fmaxf(l2,0.f), fmaxf(h2,0.f), fmaxf(l3,0.f), fmaxf(h3,0.f) };
            o0[q] = v0;
            o1[q] = v1;
        }
    }
}

extern "C" void kernel_launch(void* const* d_in, const int* in_sizes, int n_in,
                              void* d_out, int out_size) {
    const float* user_emb = (const float*)d_in[0];
    const float* item_emb = (const float*)d_in[1];
    float* out = (float*)d_out;
    const int B = in_sizes[1] / PARAMS;        // 16384
    can_kernel<<<B / WPC, THREADS>>>(user_emb, item_emb, out);
}